// round 16
// baseline (speedup 1.0000x reference)
#include <cuda_runtime.h>
#include <cuda_bf16.h>
#include <math.h>
#include <stdint.h>

#define N   384
#define C   128
#define H   4
#define DH  32
#define NN  (N*N)
#define LOG2E 1.4426950408889634f
typedef unsigned long long ull;
typedef uint32_t u32;

// Scratch (allocation-free rule: __device__ globals)
__device__ __align__(16) float g_g[NN*C];
__device__ __align__(16) float g_o[NN*C];
__device__ __align__(16) float g_bias[H*NN];   // frag order, pre-scaled by log2e
__device__ __align__(16) __nv_bfloat16 g_xh[NN*C], g_xl[NN*C];
__device__ __align__(16) __nv_bfloat16 g_qh[NN*C];          // Q: hi only
__device__ __align__(16) __nv_bfloat16 g_kh[NN*C];          // K: hi only
__device__ __align__(16) __nv_bfloat16 g_vh[NN*C], g_vl[NN*C];  // V: SPLIT
__device__ __align__(16) uint4 g_wfh[5*2048], g_wfl[5*2048]; // fragment-ordered W

// --------------------------- helpers ---------------------------------------
__device__ __forceinline__ u32 pack_bf2(float a, float b) {   // a->low, b->high
    __nv_bfloat162 t = __floats2bfloat162_rn(a, b); return *(u32*)&t;
}
__device__ __forceinline__ float lo_f(u32 u) { return __uint_as_float(u << 16); }
__device__ __forceinline__ float hi_f(u32 u) { return __uint_as_float(u & 0xFFFF0000u); }
__device__ __forceinline__ u32 smem_u32(const void* p) {
    u32 a; asm("{ .reg .u64 t; cvta.to.shared.u64 t, %1; cvt.u32.u64 %0, t; }"
               : "=r"(a) : "l"(p));
    return a;
}
__device__ __forceinline__ float ex2(float x) {
    float r; asm("ex2.approx.ftz.f32 %0, %1;" : "=f"(r) : "f"(x)); return r;
}
// bf16 warp MMA: D[16x8] += A[16x16] * B[16x8] (A row-major, B col-major)
__device__ __forceinline__ void mma16816(float* d, const u32* a, u32 b0, u32 b1) {
    asm volatile("mma.sync.aligned.m16n8k16.row.col.f32.bf16.bf16.f32 "
        "{%0,%1,%2,%3}, {%4,%5,%6,%7}, {%8,%9}, {%0,%1,%2,%3};"
        : "+f"(d[0]), "+f"(d[1]), "+f"(d[2]), "+f"(d[3])
        : "r"(a[0]), "r"(a[1]), "r"(a[2]), "r"(a[3]), "r"(b0), "r"(b1));
}
__device__ __forceinline__ void ldsm4(u32* r, u32 addr) {
    asm volatile("ldmatrix.sync.aligned.m8n8.x4.shared.b16 {%0,%1,%2,%3}, [%4];"
        : "=r"(r[0]), "=r"(r[1]), "=r"(r[2]), "=r"(r[3]) : "r"(addr));
}

// ---------------------------------------------------------------------------
// Weight prep: W (k-major [k][n]) -> MMA B-fragment order, split hi/lo.
// ---------------------------------------------------------------------------
__global__ void prep_w_kernel(const float* __restrict__ wq, const float* __restrict__ wk,
                              const float* __restrict__ wv, const float* __restrict__ wg,
                              const float* __restrict__ wo) {
    int w = blockIdx.x;
    const float* W = (w == 0) ? wq : (w == 1) ? wk : (w == 2) ? wv : (w == 3) ? wg : wo;
    uint4* fh = g_wfh + (size_t)w*2048;
    uint4* fl = g_wfl + (size_t)w*2048;
    for (int i = threadIdx.x; i < 2048; i += blockDim.x) {
        int ntile = i >> 8, ks = (i >> 5) & 7, lane = i & 31;
        int n0 = ntile*16 + (lane >> 2);
        int k0 = ks*16 + (lane & 3)*2;
        float a0 = W[k0*C + n0],       a1 = W[(k0+1)*C + n0];
        float b0 = W[k0*C + n0+8],     b1 = W[(k0+1)*C + n0+8];
        float c0 = W[(k0+8)*C + n0],   c1 = W[(k0+9)*C + n0];
        float d0 = W[(k0+8)*C + n0+8], d1 = W[(k0+9)*C + n0+8];
        uint4 h, l;
        h.x = pack_bf2(a0, a1);  l.x = pack_bf2(a0 - lo_f(h.x), a1 - hi_f(h.x));
        h.y = pack_bf2(b0, b1);  l.y = pack_bf2(b0 - lo_f(h.y), b1 - hi_f(h.y));
        h.z = pack_bf2(c0, c1);  l.z = pack_bf2(c0 - lo_f(h.z), c1 - hi_f(h.z));
        h.w = pack_bf2(d0, d1);  l.w = pack_bf2(d0 - lo_f(h.w), d1 - hi_f(h.w));
        fh[i] = h;  fl[i] = l;
    }
}

// ---------------------------------------------------------------------------
// LayerNorm + per-head pair bias; x written as SPLIT bf16.
// Bias written in MMA D-fragment order, PRE-SCALED by log2(e).
// ---------------------------------------------------------------------------
__global__ void ln_bias_kernel(const float* __restrict__ pair,
                               const float* __restrict__ ln_w,
                               const float* __restrict__ ln_b,
                               const float* __restrict__ w_bias) {
    int warp = threadIdx.x >> 5, lane = threadIdx.x & 31;
    int row0 = (blockIdx.x * 8 + warp) * 2;
    float4 lw = ((const float4*)ln_w)[lane];
    float4 lb = ((const float4*)ln_b)[lane];
    float4 wb0 = ((const float4*)w_bias)[lane*4 + 0];
    float4 wb1 = ((const float4*)w_bias)[lane*4 + 1];
    float4 wb2 = ((const float4*)w_bias)[lane*4 + 2];
    float4 wb3 = ((const float4*)w_bias)[lane*4 + 3];
    #pragma unroll
    for (int rr = 0; rr < 2; rr++) {
        int row = row0 + rr;
        float4 x = ((const float4*)(pair + (size_t)row * C))[lane];
        float s = x.x + x.y + x.z + x.w;
        #pragma unroll
        for (int o = 16; o; o >>= 1) s += __shfl_xor_sync(0xffffffffu, s, o);
        float mu = s * (1.0f / C);
        float dx = x.x-mu, dy = x.y-mu, dz = x.z-mu, dw = x.w-mu;
        float s2 = dx*dx + dy*dy + dz*dz + dw*dw;
        #pragma unroll
        for (int o = 16; o; o >>= 1) s2 += __shfl_xor_sync(0xffffffffu, s2, o);
        float rstd = rsqrtf(s2 * (1.0f / C) + 1e-5f);
        float4 y;
        y.x = dx*rstd*lw.x + lb.x;  y.y = dy*rstd*lw.y + lb.y;
        y.z = dz*rstd*lw.z + lb.z;  y.w = dw*rstd*lw.w + lb.w;
        u32 h0 = pack_bf2(y.x, y.y), h1 = pack_bf2(y.z, y.w);
        u32 l0 = pack_bf2(y.x - lo_f(h0), y.y - hi_f(h0));
        u32 l1 = pack_bf2(y.z - lo_f(h1), y.w - hi_f(h1));
        ((u32*)g_xh)[(size_t)row*64 + lane*2]     = h0;
        ((u32*)g_xh)[(size_t)row*64 + lane*2 + 1] = h1;
        ((u32*)g_xl)[(size_t)row*64 + lane*2]     = l0;
        ((u32*)g_xl)[(size_t)row*64 + lane*2 + 1] = l1;
        float4 bs;
        bs.x = y.x*wb0.x + y.y*wb1.x + y.z*wb2.x + y.w*wb3.x;
        bs.y = y.x*wb0.y + y.y*wb1.y + y.z*wb2.y + y.w*wb3.y;
        bs.z = y.x*wb0.z + y.y*wb1.z + y.z*wb2.z + y.w*wb3.z;
        bs.w = y.x*wb0.w + y.y*wb1.w + y.z*wb2.w + y.w*wb3.w;
        #pragma unroll
        for (int o = 16; o; o >>= 1) {
            bs.x += __shfl_xor_sync(0xffffffffu, bs.x, o);
            bs.y += __shfl_xor_sync(0xffffffffu, bs.y, o);
            bs.z += __shfl_xor_sync(0xffffffffu, bs.z, o);
            bs.w += __shfl_xor_sync(0xffffffffu, bs.w, o);
        }
        if (lane == 0) {
            int q = row / N, k = row - q * N;
            int qt = q >> 4, qlc = q & 15, kt = k >> 4, klc = k & 15;
            int fl_lane = (qlc & 7)*4 + ((klc & 7) >> 1);
            size_t base = ((size_t)(qt*24 + kt)*32 + fl_lane)*8
                        + (klc >> 3)*4 + ((qlc >> 3)*2 + (klc & 1));
            g_bias[0*NN + base] = bs.x * LOG2E;  g_bias[1*NN + base] = bs.y * LOG2E;
            g_bias[2*NN + base] = bs.z * LOG2E;  g_bias[3*NN + base] = bs.w * LOG2E;
        }
    }
}

// ---------------------------------------------------------------------------
// Barrier-free GEMM core (256 thr, 8 warps, warp tile 64x32).
// smem u32 layout: Ah[128*68] | Al[128*68]
// ---------------------------------------------------------------------------
#define PSM_A_H 0
#define PSM_A_L (128*68)
#define PROJ_SMEM_BYTES (2*128*68*4)

__device__ __forceinline__ void gemm_core_frag(
    u32 sb, const uint4* __restrict__ fh, const uint4* __restrict__ fl,
    int wm, int wn, int lane, float acc[4][4][4])
{
    int lr = (lane & 7) + ((lane >> 3) & 1) * 8;
    int lc = (lane >> 4) * 4;
    #pragma unroll
    for (int ks = 0; ks < 8; ks++) {
        u32 ah[4][4], al[4][4];
        #pragma unroll
        for (int mt = 0; mt < 4; mt++) {
            u32 aH = sb + 4*(PSM_A_H + (wm*64 + mt*16 + lr)*68 + ks*8 + lc);
            ldsm4(ah[mt], aH);
            ldsm4(al[mt], aH + 4*(PSM_A_L - PSM_A_H));
        }
        #pragma unroll
        for (int nt = 0; nt < 2; nt++) {
            uint4 bh = fh[((wn*2 + nt)*8 + ks)*32 + lane];
            uint4 bl = fl[((wn*2 + nt)*8 + ks)*32 + lane];
            #pragma unroll
            for (int mt = 0; mt < 4; mt++) {
                float* a0 = acc[mt][nt*2];
                float* a1 = acc[mt][nt*2+1];
                mma16816(a0, ah[mt], bh.x, bh.z);
                mma16816(a1, ah[mt], bh.y, bh.w);
                mma16816(a0, ah[mt], bl.x, bl.z);
                mma16816(a1, ah[mt], bl.y, bl.w);
                mma16816(a0, al[mt], bh.x, bh.z);
                mma16816(a1, al[mt], bh.y, bh.w);
            }
        }
    }
}

// ---------------------------------------------------------------------------
// QKVG projections. Q/K: hi only; V: hi+lo; gate: sigmoid fp32.
// ---------------------------------------------------------------------------
__global__ __launch_bounds__(256, 2) void proj_mma_kernel() {
    extern __shared__ u32 smu[];
    u32 sb = smem_u32(smu);
    int tid = threadIdx.x, wid = tid >> 5, lane = tid & 31;
    int wm = wid & 1, wn = wid >> 1;          // warp tile 64m x 32n
    int g = lane >> 2, t = lane & 3;
    int rowBase = blockIdx.x * 128;

    const u32* xh = (const u32*)g_xh + (size_t)rowBase*64;
    const u32* xl = (const u32*)g_xl + (size_t)rowBase*64;
    for (int i = tid; i < 128*64; i += 256) {
        int row = i >> 6, c = i & 63;
        smu[PSM_A_H + row*68 + c] = xh[row*64 + c];
        smu[PSM_A_L + row*68 + c] = xl[row*64 + c];
    }
    __syncthreads();

    #pragma unroll
    for (int w = 0; w < 4; w++) {
        const uint4* fh = g_wfh + (size_t)w*2048;
        const uint4* fl = g_wfl + (size_t)w*2048;
        float acc[4][4][4];
        #pragma unroll
        for (int mt = 0; mt < 4; mt++)
            #pragma unroll
            for (int nf = 0; nf < 4; nf++)
                #pragma unroll
                for (int j = 0; j < 4; j++) acc[mt][nf][j] = 0.f;
        gemm_core_frag(sb, fh, fl, wm, wn, lane, acc);

        #pragma unroll
        for (int mt = 0; mt < 4; mt++) {
            size_t row0 = (size_t)rowBase + wm*64 + mt*16 + g;
            size_t row1 = row0 + 8;
            if (w < 3) {
                u32* Oh = (u32*)((w == 0) ? g_qh : (w == 1) ? g_kh : g_vh);
                #pragma unroll
                for (int nf = 0; nf < 4; nf++) {
                    int cp = wn*16 + nf*4 + t;
                    float* a = acc[mt][nf];
                    u32 h0 = pack_bf2(a[0], a[1]);
                    u32 h1 = pack_bf2(a[2], a[3]);
                    Oh[row0*64 + cp] = h0;
                    Oh[row1*64 + cp] = h1;
                    if (w == 2) {   // V keeps the lo split (error passes through)
                        u32* Ol = (u32*)g_vl;
                        Ol[row0*64 + cp] = pack_bf2(a[0] - lo_f(h0), a[1] - hi_f(h0));
                        Ol[row1*64 + cp] = pack_bf2(a[2] - lo_f(h1), a[3] - hi_f(h1));
                    }
                }
            } else {
                #pragma unroll
                for (int nf = 0; nf < 4; nf++) {
                    int col = wn*32 + nf*8 + 2*t;
                    float* a = acc[mt][nf];
                    float2 v0, v1;
                    v0.x = 1.f/(1.f + __expf(-a[0]));
                    v0.y = 1.f/(1.f + __expf(-a[1]));
                    v1.x = 1.f/(1.f + __expf(-a[2]));
                    v1.y = 1.f/(1.f + __expf(-a[3]));
                    *(float2*)&g_g[row0*C + col] = v0;
                    *(float2*)&g_g[row1*C + col] = v1;
                }
            }
        }
    }
}

// ---------------------------------------------------------------------------
// Output projection: (o * gate) @ wo -> fp32 d_out.
// ---------------------------------------------------------------------------
__global__ __launch_bounds__(256, 2) void out_mma_kernel(float* __restrict__ Out) {
    extern __shared__ u32 smu[];
    u32 sb = smem_u32(smu);
    int tid = threadIdx.x, wid = tid >> 5, lane = tid & 31;
    int wm = wid & 1, wn = wid >> 1;
    int g = lane >> 2, t = lane & 3;
    int rowBase = blockIdx.x * 128;

    const float4* op = (const float4*)(g_o + (size_t)rowBase*C);
    const float4* gp = (const float4*)(g_g + (size_t)rowBase*C);
    for (int i = tid; i < 128*32; i += 256) {
        int row = i >> 5, c = i & 31;
        float4 a = op[row*32 + c], b = gp[row*32 + c];
        a.x *= b.x; a.y *= b.y; a.z *= b.z; a.w *= b.w;
        u32 h0 = pack_bf2(a.x, a.y), h1 = pack_bf2(a.z, a.w);
        smu[PSM_A_H + row*68 + 2*c]     = h0;
        smu[PSM_A_H + row*68 + 2*c + 1] = h1;
        smu[PSM_A_L + row*68 + 2*c]     = pack_bf2(a.x - lo_f(h0), a.y - hi_f(h0));
        smu[PSM_A_L + row*68 + 2*c + 1] = pack_bf2(a.z - lo_f(h1), a.w - hi_f(h1));
    }
    __syncthreads();

    const uint4* fh = g_wfh + (size_t)4*2048;
    const uint4* fl = g_wfl + (size_t)4*2048;
    float acc[4][4][4];
    #pragma unroll
    for (int mt = 0; mt < 4; mt++)
        #pragma unroll
        for (int nf = 0; nf < 4; nf++)
            #pragma unroll
            for (int j = 0; j < 4; j++) acc[mt][nf][j] = 0.f;
    gemm_core_frag(sb, fh, fl, wm, wn, lane, acc);

    #pragma unroll
    for (int mt = 0; mt < 4; mt++) {
        size_t row0 = (size_t)rowBase + wm*64 + mt*16 + g;
        size_t row1 = row0 + 8;
        #pragma unroll
        for (int nf = 0; nf < 4; nf++) {
            int col = wn*32 + nf*8 + 2*t;
            float* a = acc[mt][nf];
            *(float2*)&Out[row0*C + col] = make_float2(a[0], a[1]);
            *(float2*)&Out[row1*C + col] = make_float2(a[2], a[3]);
        }
    }
}

// ---------------------------------------------------------------------------
// Attention: QK single-bf16 (4 MMAs); P split x V split (12 MMAs).
// exp2 softmax with prescaled bias/mask; fragment-ordered bias loads.
// SMEM: madd[384] | Kh [384][40 bf16] | Vth/Vtl [32][392 bf16].
// ---------------------------------------------------------------------------
#define SM_MADD 0
#define SM_KH   1536
#define SM_VTH  (SM_KH + 30720)
#define SM_VTL  (SM_VTH + 25088)
#define AT_SMEM (SM_VTL + 25088)

__global__ __launch_bounds__(384, 2) void attn_mma_kernel(const int* __restrict__ mask) {
    extern __shared__ char smem[];
    u32 sb = smem_u32(smem);
    float* madd = (float*)(smem + SM_MADD);
    u32* Khs = (u32*)(smem + SM_KH);              // row stride 20 u32
    uint16_t* Vth = (uint16_t*)(smem + SM_VTH);   // [32 d][392 keys]
    uint16_t* Vtl = (uint16_t*)(smem + SM_VTL);

    int b = blockIdx.x, h = blockIdx.y;
    int tid = threadIdx.x, warp = tid >> 5, lane = tid & 31;
    int g = lane >> 2, t = lane & 3;
    int lr = (lane & 7) + ((lane >> 3) & 1) * 8;
    int lc = (lane >> 4) * 4;
    const float scale2 = 0.17677669529663687f * LOG2E;

    const u32* KH = (const u32*)g_kh;
    const u32* VH = (const u32*)g_vh;  const u32* VL = (const u32*)g_vl;
    const u32* QH = (const u32*)g_qh;

    for (int i = tid; i < N; i += 384)
        madd[i] = ((mask[b*N + i] > 0 ? 0.f : -1e9f) - 4.0f) * LOG2E;
    for (int i = tid; i < N*16; i += 384) {
        int key = i >> 4, dp = i & 15;
        size_t gi = (size_t)(b*N + key)*64 + h*16 + dp;
        Khs[key*20 + dp] = KH[gi];
        u32 vh = VH[gi], vl = VL[gi];
        Vth[(2*dp)*392 + key]   = (uint16_t)(vh & 0xFFFFu);
        Vth[(2*dp+1)*392 + key] = (uint16_t)(vh >> 16);
        Vtl[(2*dp)*392 + key]   = (uint16_t)(vl & 0xFFFFu);
        Vtl[(2*dp+1)*392 + key] = (uint16_t)(vl >> 16);
    }
    __syncthreads();

    for (int mt = 0; mt < 2; mt++) {
        int qb = warp*32 + mt*16;
        u32 qh[2][4];
        #pragma unroll
        for (int ks = 0; ks < 2; ks++) {
            size_t base0 = (size_t)(b*N + qb + g)*64 + h*16 + ks*8 + t;
            size_t base1 = base0 + 8*64;
            qh[ks][0] = QH[base0];     qh[ks][1] = QH[base1];
            qh[ks][2] = QH[base0 + 4]; qh[ks][3] = QH[base1 + 4];
        }
        float oacc[4][4];
        #pragma unroll
        for (int dt = 0; dt < 4; dt++)
            #pragma unroll
            for (int j = 0; j < 4; j++) oacc[dt][j] = 0.f;
        float sum0 = 0.f, sum1 = 0.f;
        // fragment-ordered bias tile row for this (h, qtile)
        const float4* bfr = (const float4*)g_bias
                          + ((size_t)h*576 + (size_t)(warp*2 + mt)*24) * 64 + lane*2;

        for (int kb = 0; kb < N; kb += 16) {
            u32 kh[2][4];
            #pragma unroll
            for (int ks = 0; ks < 2; ks++)
                ldsm4(kh[ks], sb + SM_KH + ((kb + lr)*20 + ks*8 + lc)*4);
            float s0[4] = {0.f,0.f,0.f,0.f}, s1[4] = {0.f,0.f,0.f,0.f};
            #pragma unroll
            for (int ks = 0; ks < 2; ks++) {
                mma16816(s0, qh[ks], kh[ks][0], kh[ks][2]);
                mma16816(s1, qh[ks], kh[ks][1], kh[ks][3]);
            }
            float4 f0 = bfr[(kb >> 4)*64];
            float4 f1 = bfr[(kb >> 4)*64 + 1];
            float2 mA0 = *(const float2*)&madd[kb + 2*t];
            float2 mA1 = *(const float2*)&madd[kb + 8 + 2*t];
            float e00 = ex2(fmaf(s0[0], scale2, f0.x + mA0.x));
            float e01 = ex2(fmaf(s0[1], scale2, f0.y + mA0.y));
            float e02 = ex2(fmaf(s0[2], scale2, f0.z + mA0.x));
            float e03 = ex2(fmaf(s0[3], scale2, f0.w + mA0.y));
            float e10 = ex2(fmaf(s1[0], scale2, f1.x + mA1.x));
            float e11 = ex2(fmaf(s1[1], scale2, f1.y + mA1.y));
            float e12 = ex2(fmaf(s1[2], scale2, f1.z + mA1.x));
            float e13 = ex2(fmaf(s1[3], scale2, f1.w + mA1.y));
            sum0 += (e00 + e01) + (e10 + e11);
            sum1 += (e02 + e03) + (e12 + e13);
            u32 ah[4], al[4];
            ah[0] = pack_bf2(e00, e01);  ah[1] = pack_bf2(e02, e03);
            ah[2] = pack_bf2(e10, e11);  ah[3] = pack_bf2(e12, e13);
            al[0] = pack_bf2(e00 - lo_f(ah[0]), e01 - hi_f(ah[0]));
            al[1] = pack_bf2(e02 - lo_f(ah[1]), e03 - hi_f(ah[1]));
            al[2] = pack_bf2(e10 - lo_f(ah[2]), e11 - hi_f(ah[2]));
            al[3] = pack_bf2(e12 - lo_f(ah[3]), e13 - hi_f(ah[3]));
            #pragma unroll
            for (int dh = 0; dh < 2; dh++) {
                u32 vh[4], vl[4];
                u32 aH = sb + SM_VTH + ((dh*16 + lr)*196 + (kb >> 1) + lc)*4;
                ldsm4(vh, aH);
                ldsm4(vl, aH + (SM_VTL - SM_VTH));
                mma16816(oacc[dh*2],   ah, vh[0], vh[2]);
                mma16816(oacc[dh*2+1], ah, vh[1], vh[3]);
                mma16816(oacc[dh*2],   ah, vl[0], vl[2]);
                mma16816(oacc[dh*2+1], ah, vl[1], vl[3]);
                mma16816(oacc[dh*2],   al, vh[0], vh[2]);
                mma16816(oacc[dh*2+1], al, vh[1], vh[3]);
            }
        }
        sum0 += __shfl_xor_sync(0xffffffffu, sum0, 1);
        sum0 += __shfl_xor_sync(0xffffffffu, sum0, 2);
        sum1 += __shfl_xor_sync(0xffffffffu, sum1, 1);
        sum1 += __shfl_xor_sync(0xffffffffu, sum1, 2);
        float inv0 = 1.f / sum0, inv1 = 1.f / sum1;
        float* o0 = g_o + (size_t)(b*N + qb + g)*C + h*DH;
        float* o1 = o0 + 8*C;
        #pragma unroll
        for (int dt = 0; dt < 4; dt++) {
            *(float2*)&o0[dt*8 + 2*t] = make_float2(oacc[dt][0]*inv0, oacc[dt][1]*inv0);
            *(float2*)&o1[dt*8 + 2*t] = make_float2(oacc[dt][2]*inv1, oacc[dt][3]*inv1);
        }
    }
}

// ---------------------------------------------------------------------------
extern "C" void kernel_launch(void* const* d_in, const int* in_sizes, int n_in,
                              void* d_out, int out_size) {
    const float* pair   = (const float*)d_in[0];
    const int*   mask   = (const int*)  d_in[1];
    const float* ln_w   = (const float*)d_in[2];
    const float* ln_b   = (const float*)d_in[3];
    const float* w_bias = (const float*)d_in[4];
    const float* wq     = (const float*)d_in[5];
    const float* wk     = (const float*)d_in[6];
    const float* wv     = (const float*)d_in[7];
    const float* wg     = (const float*)d_in[8];
    const float* wo     = (const float*)d_in[9];

    cudaFuncSetAttribute(proj_mma_kernel, cudaFuncAttributeMaxDynamicSharedMemorySize,
                         PROJ_SMEM_BYTES);
    cudaFuncSetAttribute(out_mma_kernel, cudaFuncAttributeMaxDynamicSharedMemorySize,
                         PROJ_SMEM_BYTES);
    cudaFuncSetAttribute(attn_mma_kernel, cudaFuncAttributeMaxDynamicSharedMemorySize,
                         AT_SMEM);

    prep_w_kernel<<<5, 256>>>(wq, wk, wv, wg, wo);
    ln_bias_kernel<<<NN/16, 256>>>(pair, ln_w, ln_b, w_bias);
    proj_mma_kernel<<<NN/128, 256, PROJ_SMEM_BYTES>>>();
    attn_mma_kernel<<<dim3(N, H), 384, AT_SMEM>>>(mask);
    out_mma_kernel<<<NN/128, 256, PROJ_SMEM_BYTES>>>((float*)d_out);
}

// round 17
// speedup vs baseline: 1.4328x; 1.4328x over previous
#include <cuda_runtime.h>
#include <cuda_bf16.h>
#include <math.h>
#include <stdint.h>

#define N   384
#define C   128
#define H   4
#define DH  32
#define NN  (N*N)
#define LOG2E 1.4426950408889634f
typedef unsigned long long ull;
typedef uint32_t u32;

// Scratch (allocation-free rule: __device__ globals)
__device__ __align__(16) float g_g[NN*C];
__device__ __align__(16) float g_o[NN*C];
__device__ __align__(16) float g_bias[H*NN];   // frag order, pre-scaled by log2e
__device__ __align__(16) __nv_bfloat16 g_xh[NN*C], g_xl[NN*C];
__device__ __align__(16) __nv_bfloat16 g_qh[NN*C];          // Q: hi only
__device__ __align__(16) __nv_bfloat16 g_kh[NN*C];          // K: hi only
__device__ __align__(16) __nv_bfloat16 g_vh[NN*C], g_vl[NN*C];  // V: SPLIT
__device__ __align__(16) uint4 g_wfh[5*2048], g_wfl[5*2048]; // fragment-ordered W

// --------------------------- helpers ---------------------------------------
__device__ __forceinline__ u32 pack_bf2(float a, float b) {   // a->low, b->high
    __nv_bfloat162 t = __floats2bfloat162_rn(a, b); return *(u32*)&t;
}
__device__ __forceinline__ float lo_f(u32 u) { return __uint_as_float(u << 16); }
__device__ __forceinline__ float hi_f(u32 u) { return __uint_as_float(u & 0xFFFF0000u); }
__device__ __forceinline__ u32 smem_u32(const void* p) {
    u32 a; asm("{ .reg .u64 t; cvta.to.shared.u64 t, %1; cvt.u32.u64 %0, t; }"
               : "=r"(a) : "l"(p));
    return a;
}
__device__ __forceinline__ float ex2(float x) {
    float r; asm("ex2.approx.ftz.f32 %0, %1;" : "=f"(r) : "f"(x)); return r;
}
// bf16 warp MMA: D[16x8] += A[16x16] * B[16x8] (A row-major, B col-major)
__device__ __forceinline__ void mma16816(float* d, const u32* a, u32 b0, u32 b1) {
    asm volatile("mma.sync.aligned.m16n8k16.row.col.f32.bf16.bf16.f32 "
        "{%0,%1,%2,%3}, {%4,%5,%6,%7}, {%8,%9}, {%0,%1,%2,%3};"
        : "+f"(d[0]), "+f"(d[1]), "+f"(d[2]), "+f"(d[3])
        : "r"(a[0]), "r"(a[1]), "r"(a[2]), "r"(a[3]), "r"(b0), "r"(b1));
}
__device__ __forceinline__ void ldsm4(u32* r, u32 addr) {
    asm volatile("ldmatrix.sync.aligned.m8n8.x4.shared.b16 {%0,%1,%2,%3}, [%4];"
        : "=r"(r[0]), "=r"(r[1]), "=r"(r[2]), "=r"(r[3]) : "r"(addr));
}

// ---------------------------------------------------------------------------
// Weight prep: W (k-major [k][n]) -> MMA B-fragment order, split hi/lo.
// ---------------------------------------------------------------------------
__global__ void prep_w_kernel(const float* __restrict__ wq, const float* __restrict__ wk,
                              const float* __restrict__ wv, const float* __restrict__ wg,
                              const float* __restrict__ wo) {
    int w = blockIdx.x;
    const float* W = (w == 0) ? wq : (w == 1) ? wk : (w == 2) ? wv : (w == 3) ? wg : wo;
    uint4* fh = g_wfh + (size_t)w*2048;
    uint4* fl = g_wfl + (size_t)w*2048;
    for (int i = threadIdx.x; i < 2048; i += blockDim.x) {
        int ntile = i >> 8, ks = (i >> 5) & 7, lane = i & 31;
        int n0 = ntile*16 + (lane >> 2);
        int k0 = ks*16 + (lane & 3)*2;
        float a0 = W[k0*C + n0],       a1 = W[(k0+1)*C + n0];
        float b0 = W[k0*C + n0+8],     b1 = W[(k0+1)*C + n0+8];
        float c0 = W[(k0+8)*C + n0],   c1 = W[(k0+9)*C + n0];
        float d0 = W[(k0+8)*C + n0+8], d1 = W[(k0+9)*C + n0+8];
        uint4 h, l;
        h.x = pack_bf2(a0, a1);  l.x = pack_bf2(a0 - lo_f(h.x), a1 - hi_f(h.x));
        h.y = pack_bf2(b0, b1);  l.y = pack_bf2(b0 - lo_f(h.y), b1 - hi_f(h.y));
        h.z = pack_bf2(c0, c1);  l.z = pack_bf2(c0 - lo_f(h.z), c1 - hi_f(h.z));
        h.w = pack_bf2(d0, d1);  l.w = pack_bf2(d0 - lo_f(h.w), d1 - hi_f(h.w));
        fh[i] = h;  fl[i] = l;
    }
}

// ---------------------------------------------------------------------------
// LayerNorm + per-head pair bias; x written as SPLIT bf16.
// Bias written in MMA D-fragment order, PRE-SCALED by log2(e).
// ---------------------------------------------------------------------------
__global__ void ln_bias_kernel(const float* __restrict__ pair,
                               const float* __restrict__ ln_w,
                               const float* __restrict__ ln_b,
                               const float* __restrict__ w_bias) {
    int warp = threadIdx.x >> 5, lane = threadIdx.x & 31;
    int row0 = (blockIdx.x * 8 + warp) * 2;
    float4 lw = ((const float4*)ln_w)[lane];
    float4 lb = ((const float4*)ln_b)[lane];
    float4 wb0 = ((const float4*)w_bias)[lane*4 + 0];
    float4 wb1 = ((const float4*)w_bias)[lane*4 + 1];
    float4 wb2 = ((const float4*)w_bias)[lane*4 + 2];
    float4 wb3 = ((const float4*)w_bias)[lane*4 + 3];
    #pragma unroll
    for (int rr = 0; rr < 2; rr++) {
        int row = row0 + rr;
        float4 x = ((const float4*)(pair + (size_t)row * C))[lane];
        float s = x.x + x.y + x.z + x.w;
        #pragma unroll
        for (int o = 16; o; o >>= 1) s += __shfl_xor_sync(0xffffffffu, s, o);
        float mu = s * (1.0f / C);
        float dx = x.x-mu, dy = x.y-mu, dz = x.z-mu, dw = x.w-mu;
        float s2 = dx*dx + dy*dy + dz*dz + dw*dw;
        #pragma unroll
        for (int o = 16; o; o >>= 1) s2 += __shfl_xor_sync(0xffffffffu, s2, o);
        float rstd = rsqrtf(s2 * (1.0f / C) + 1e-5f);
        float4 y;
        y.x = dx*rstd*lw.x + lb.x;  y.y = dy*rstd*lw.y + lb.y;
        y.z = dz*rstd*lw.z + lb.z;  y.w = dw*rstd*lw.w + lb.w;
        u32 h0 = pack_bf2(y.x, y.y), h1 = pack_bf2(y.z, y.w);
        u32 l0 = pack_bf2(y.x - lo_f(h0), y.y - hi_f(h0));
        u32 l1 = pack_bf2(y.z - lo_f(h1), y.w - hi_f(h1));
        ((u32*)g_xh)[(size_t)row*64 + lane*2]     = h0;
        ((u32*)g_xh)[(size_t)row*64 + lane*2 + 1] = h1;
        ((u32*)g_xl)[(size_t)row*64 + lane*2]     = l0;
        ((u32*)g_xl)[(size_t)row*64 + lane*2 + 1] = l1;
        float4 bs;
        bs.x = y.x*wb0.x + y.y*wb1.x + y.z*wb2.x + y.w*wb3.x;
        bs.y = y.x*wb0.y + y.y*wb1.y + y.z*wb2.y + y.w*wb3.y;
        bs.z = y.x*wb0.z + y.y*wb1.z + y.z*wb2.z + y.w*wb3.z;
        bs.w = y.x*wb0.w + y.y*wb1.w + y.z*wb2.w + y.w*wb3.w;
        #pragma unroll
        for (int o = 16; o; o >>= 1) {
            bs.x += __shfl_xor_sync(0xffffffffu, bs.x, o);
            bs.y += __shfl_xor_sync(0xffffffffu, bs.y, o);
            bs.z += __shfl_xor_sync(0xffffffffu, bs.z, o);
            bs.w += __shfl_xor_sync(0xffffffffu, bs.w, o);
        }
        if (lane == 0) {
            int q = row / N, k = row - q * N;
            int qt = q >> 4, qlc = q & 15, kt = k >> 4, klc = k & 15;
            int fl_lane = (qlc & 7)*4 + ((klc & 7) >> 1);
            size_t base = ((size_t)(qt*24 + kt)*32 + fl_lane)*8
                        + (klc >> 3)*4 + ((qlc >> 3)*2 + (klc & 1));
            g_bias[0*NN + base] = bs.x * LOG2E;  g_bias[1*NN + base] = bs.y * LOG2E;
            g_bias[2*NN + base] = bs.z * LOG2E;  g_bias[3*NN + base] = bs.w * LOG2E;
        }
    }
}

// ---------------------------------------------------------------------------
// Barrier-free GEMM core (256 thr, 8 warps, warp tile 64x32).
// smem u32 layout: Ah[128*68] | Al[128*68]
// ---------------------------------------------------------------------------
#define PSM_A_H 0
#define PSM_A_L (128*68)
#define PROJ_SMEM_BYTES (2*128*68*4)

__device__ __forceinline__ void gemm_core_frag(
    u32 sb, const uint4* __restrict__ fh, const uint4* __restrict__ fl,
    int wm, int wn, int lane, float acc[4][4][4])
{
    int lr = (lane & 7) + ((lane >> 3) & 1) * 8;
    int lc = (lane >> 4) * 4;
    #pragma unroll
    for (int ks = 0; ks < 8; ks++) {
        u32 ah[4][4], al[4][4];
        #pragma unroll
        for (int mt = 0; mt < 4; mt++) {
            u32 aH = sb + 4*(PSM_A_H + (wm*64 + mt*16 + lr)*68 + ks*8 + lc);
            ldsm4(ah[mt], aH);
            ldsm4(al[mt], aH + 4*(PSM_A_L - PSM_A_H));
        }
        #pragma unroll
        for (int nt = 0; nt < 2; nt++) {
            uint4 bh = fh[((wn*2 + nt)*8 + ks)*32 + lane];
            uint4 bl = fl[((wn*2 + nt)*8 + ks)*32 + lane];
            #pragma unroll
            for (int mt = 0; mt < 4; mt++) {
                float* a0 = acc[mt][nt*2];
                float* a1 = acc[mt][nt*2+1];
                mma16816(a0, ah[mt], bh.x, bh.z);
                mma16816(a1, ah[mt], bh.y, bh.w);
                mma16816(a0, ah[mt], bl.x, bl.z);
                mma16816(a1, ah[mt], bl.y, bl.w);
                mma16816(a0, al[mt], bh.x, bh.z);
                mma16816(a1, al[mt], bh.y, bh.w);
            }
        }
    }
}

// ---------------------------------------------------------------------------
// QKVG projections. Q/K: hi only; V: hi+lo; gate: sigmoid fp32.
// Weight loop kept ROLLED (unroll 1): full unroll quadruples the body and
// thrashes the I$ (measured +200us in R16).
// ---------------------------------------------------------------------------
__global__ __launch_bounds__(256, 2) void proj_mma_kernel() {
    extern __shared__ u32 smu[];
    u32 sb = smem_u32(smu);
    int tid = threadIdx.x, wid = tid >> 5, lane = tid & 31;
    int wm = wid & 1, wn = wid >> 1;          // warp tile 64m x 32n
    int g = lane >> 2, t = lane & 3;
    int rowBase = blockIdx.x * 128;

    const u32* xh = (const u32*)g_xh + (size_t)rowBase*64;
    const u32* xl = (const u32*)g_xl + (size_t)rowBase*64;
    for (int i = tid; i < 128*64; i += 256) {
        int row = i >> 6, c = i & 63;
        smu[PSM_A_H + row*68 + c] = xh[row*64 + c];
        smu[PSM_A_L + row*68 + c] = xl[row*64 + c];
    }
    __syncthreads();

    #pragma unroll 1
    for (int w = 0; w < 4; w++) {
        const uint4* fh = g_wfh + (size_t)w*2048;
        const uint4* fl = g_wfl + (size_t)w*2048;
        float acc[4][4][4];
        #pragma unroll
        for (int mt = 0; mt < 4; mt++)
            #pragma unroll
            for (int nf = 0; nf < 4; nf++)
                #pragma unroll
                for (int j = 0; j < 4; j++) acc[mt][nf][j] = 0.f;
        gemm_core_frag(sb, fh, fl, wm, wn, lane, acc);

        #pragma unroll
        for (int mt = 0; mt < 4; mt++) {
            size_t row0 = (size_t)rowBase + wm*64 + mt*16 + g;
            size_t row1 = row0 + 8;
            if (w < 3) {
                u32* Oh = (u32*)((w == 0) ? g_qh : (w == 1) ? g_kh : g_vh);
                #pragma unroll
                for (int nf = 0; nf < 4; nf++) {
                    int cp = wn*16 + nf*4 + t;
                    float* a = acc[mt][nf];
                    u32 h0 = pack_bf2(a[0], a[1]);
                    u32 h1 = pack_bf2(a[2], a[3]);
                    Oh[row0*64 + cp] = h0;
                    Oh[row1*64 + cp] = h1;
                    if (w == 2) {   // V keeps the lo split (error passes through)
                        u32* Ol = (u32*)g_vl;
                        Ol[row0*64 + cp] = pack_bf2(a[0] - lo_f(h0), a[1] - hi_f(h0));
                        Ol[row1*64 + cp] = pack_bf2(a[2] - lo_f(h1), a[3] - hi_f(h1));
                    }
                }
            } else {
                #pragma unroll
                for (int nf = 0; nf < 4; nf++) {
                    int col = wn*32 + nf*8 + 2*t;
                    float* a = acc[mt][nf];
                    float2 v0, v1;
                    v0.x = 1.f/(1.f + __expf(-a[0]));
                    v0.y = 1.f/(1.f + __expf(-a[1]));
                    v1.x = 1.f/(1.f + __expf(-a[2]));
                    v1.y = 1.f/(1.f + __expf(-a[3]));
                    *(float2*)&g_g[row0*C + col] = v0;
                    *(float2*)&g_g[row1*C + col] = v1;
                }
            }
        }
    }
}

// ---------------------------------------------------------------------------
// Output projection: (o * gate) @ wo -> fp32 d_out.
// ---------------------------------------------------------------------------
__global__ __launch_bounds__(256, 2) void out_mma_kernel(float* __restrict__ Out) {
    extern __shared__ u32 smu[];
    u32 sb = smem_u32(smu);
    int tid = threadIdx.x, wid = tid >> 5, lane = tid & 31;
    int wm = wid & 1, wn = wid >> 1;
    int g = lane >> 2, t = lane & 3;
    int rowBase = blockIdx.x * 128;

    const float4* op = (const float4*)(g_o + (size_t)rowBase*C);
    const float4* gp = (const float4*)(g_g + (size_t)rowBase*C);
    for (int i = tid; i < 128*32; i += 256) {
        int row = i >> 5, c = i & 31;
        float4 a = op[row*32 + c], b = gp[row*32 + c];
        a.x *= b.x; a.y *= b.y; a.z *= b.z; a.w *= b.w;
        u32 h0 = pack_bf2(a.x, a.y), h1 = pack_bf2(a.z, a.w);
        smu[PSM_A_H + row*68 + 2*c]     = h0;
        smu[PSM_A_H + row*68 + 2*c + 1] = h1;
        smu[PSM_A_L + row*68 + 2*c]     = pack_bf2(a.x - lo_f(h0), a.y - hi_f(h0));
        smu[PSM_A_L + row*68 + 2*c + 1] = pack_bf2(a.z - lo_f(h1), a.w - hi_f(h1));
    }
    __syncthreads();

    const uint4* fh = g_wfh + (size_t)4*2048;
    const uint4* fl = g_wfl + (size_t)4*2048;
    float acc[4][4][4];
    #pragma unroll
    for (int mt = 0; mt < 4; mt++)
        #pragma unroll
        for (int nf = 0; nf < 4; nf++)
            #pragma unroll
            for (int j = 0; j < 4; j++) acc[mt][nf][j] = 0.f;
    gemm_core_frag(sb, fh, fl, wm, wn, lane, acc);

    #pragma unroll
    for (int mt = 0; mt < 4; mt++) {
        size_t row0 = (size_t)rowBase + wm*64 + mt*16 + g;
        size_t row1 = row0 + 8;
        #pragma unroll
        for (int nf = 0; nf < 4; nf++) {
            int col = wn*32 + nf*8 + 2*t;
            float* a = acc[mt][nf];
            *(float2*)&Out[row0*C + col] = make_float2(a[0], a[1]);
            *(float2*)&Out[row1*C + col] = make_float2(a[2], a[3]);
        }
    }
}

// ---------------------------------------------------------------------------
// Attention: QK single-bf16 (4 MMAs); P split x V split (12 MMAs).
// exp2 softmax with prescaled bias/mask; fragment-ordered bias loads.
// SMEM: madd[384] | Kh [384][40 bf16] | Vth/Vtl [32][392 bf16].
// ---------------------------------------------------------------------------
#define SM_MADD 0
#define SM_KH   1536
#define SM_VTH  (SM_KH + 30720)
#define SM_VTL  (SM_VTH + 25088)
#define AT_SMEM (SM_VTL + 25088)

__global__ __launch_bounds__(384, 2) void attn_mma_kernel(const int* __restrict__ mask) {
    extern __shared__ char smem[];
    u32 sb = smem_u32(smem);
    float* madd = (float*)(smem + SM_MADD);
    u32* Khs = (u32*)(smem + SM_KH);              // row stride 20 u32
    uint16_t* Vth = (uint16_t*)(smem + SM_VTH);   // [32 d][392 keys]
    uint16_t* Vtl = (uint16_t*)(smem + SM_VTL);

    int b = blockIdx.x, h = blockIdx.y;
    int tid = threadIdx.x, warp = tid >> 5, lane = tid & 31;
    int g = lane >> 2, t = lane & 3;
    int lr = (lane & 7) + ((lane >> 3) & 1) * 8;
    int lc = (lane >> 4) * 4;
    const float scale2 = 0.17677669529663687f * LOG2E;

    const u32* KH = (const u32*)g_kh;
    const u32* VH = (const u32*)g_vh;  const u32* VL = (const u32*)g_vl;
    const u32* QH = (const u32*)g_qh;

    for (int i = tid; i < N; i += 384)
        madd[i] = ((mask[b*N + i] > 0 ? 0.f : -1e9f) - 4.0f) * LOG2E;
    for (int i = tid; i < N*16; i += 384) {
        int key = i >> 4, dp = i & 15;
        size_t gi = (size_t)(b*N + key)*64 + h*16 + dp;
        Khs[key*20 + dp] = KH[gi];
        u32 vh = VH[gi], vl = VL[gi];
        Vth[(2*dp)*392 + key]   = (uint16_t)(vh & 0xFFFFu);
        Vth[(2*dp+1)*392 + key] = (uint16_t)(vh >> 16);
        Vtl[(2*dp)*392 + key]   = (uint16_t)(vl & 0xFFFFu);
        Vtl[(2*dp+1)*392 + key] = (uint16_t)(vl >> 16);
    }
    __syncthreads();

    for (int mt = 0; mt < 2; mt++) {
        int qb = warp*32 + mt*16;
        u32 qh[2][4];
        #pragma unroll
        for (int ks = 0; ks < 2; ks++) {
            size_t base0 = (size_t)(b*N + qb + g)*64 + h*16 + ks*8 + t;
            size_t base1 = base0 + 8*64;
            qh[ks][0] = QH[base0];     qh[ks][1] = QH[base1];
            qh[ks][2] = QH[base0 + 4]; qh[ks][3] = QH[base1 + 4];
        }
        float oacc[4][4];
        #pragma unroll
        for (int dt = 0; dt < 4; dt++)
            #pragma unroll
            for (int j = 0; j < 4; j++) oacc[dt][j] = 0.f;
        float sum0 = 0.f, sum1 = 0.f;
        // fragment-ordered bias tile row for this (h, qtile)
        const float4* bfr = (const float4*)g_bias
                          + ((size_t)h*576 + (size_t)(warp*2 + mt)*24) * 64 + lane*2;

        for (int kb = 0; kb < N; kb += 16) {
            u32 kh[2][4];
            #pragma unroll
            for (int ks = 0; ks < 2; ks++)
                ldsm4(kh[ks], sb + SM_KH + ((kb + lr)*20 + ks*8 + lc)*4);
            float s0[4] = {0.f,0.f,0.f,0.f}, s1[4] = {0.f,0.f,0.f,0.f};
            #pragma unroll
            for (int ks = 0; ks < 2; ks++) {
                mma16816(s0, qh[ks], kh[ks][0], kh[ks][2]);
                mma16816(s1, qh[ks], kh[ks][1], kh[ks][3]);
            }
            float4 f0 = bfr[(kb >> 4)*64];
            float4 f1 = bfr[(kb >> 4)*64 + 1];
            float2 mA0 = *(const float2*)&madd[kb + 2*t];
            float2 mA1 = *(const float2*)&madd[kb + 8 + 2*t];
            float e00 = ex2(fmaf(s0[0], scale2, f0.x + mA0.x));
            float e01 = ex2(fmaf(s0[1], scale2, f0.y + mA0.y));
            float e02 = ex2(fmaf(s0[2], scale2, f0.z + mA0.x));
            float e03 = ex2(fmaf(s0[3], scale2, f0.w + mA0.y));
            float e10 = ex2(fmaf(s1[0], scale2, f1.x + mA1.x));
            float e11 = ex2(fmaf(s1[1], scale2, f1.y + mA1.y));
            float e12 = ex2(fmaf(s1[2], scale2, f1.z + mA1.x));
            float e13 = ex2(fmaf(s1[3], scale2, f1.w + mA1.y));
            sum0 += (e00 + e01) + (e10 + e11);
            sum1 += (e02 + e03) + (e12 + e13);
            u32 ah[4], al[4];
            ah[0] = pack_bf2(e00, e01);  ah[1] = pack_bf2(e02, e03);
            ah[2] = pack_bf2(e10, e11);  ah[3] = pack_bf2(e12, e13);
            al[0] = pack_bf2(e00 - lo_f(ah[0]), e01 - hi_f(ah[0]));
            al[1] = pack_bf2(e02 - lo_f(ah[1]), e03 - hi_f(ah[1]));
            al[2] = pack_bf2(e10 - lo_f(ah[2]), e11 - hi_f(ah[2]));
            al[3] = pack_bf2(e12 - lo_f(ah[3]), e13 - hi_f(ah[3]));
            #pragma unroll
            for (int dh = 0; dh < 2; dh++) {
                u32 vh[4], vl[4];
                u32 aH = sb + SM_VTH + ((dh*16 + lr)*196 + (kb >> 1) + lc)*4;
                ldsm4(vh, aH);
                ldsm4(vl, aH + (SM_VTL - SM_VTH));
                mma16816(oacc[dh*2],   ah, vh[0], vh[2]);
                mma16816(oacc[dh*2+1], ah, vh[1], vh[3]);
                mma16816(oacc[dh*2],   ah, vl[0], vl[2]);
                mma16816(oacc[dh*2+1], ah, vl[1], vl[3]);
                mma16816(oacc[dh*2],   al, vh[0], vh[2]);
                mma16816(oacc[dh*2+1], al, vh[1], vh[3]);
            }
        }
        sum0 += __shfl_xor_sync(0xffffffffu, sum0, 1);
        sum0 += __shfl_xor_sync(0xffffffffu, sum0, 2);
        sum1 += __shfl_xor_sync(0xffffffffu, sum1, 1);
        sum1 += __shfl_xor_sync(0xffffffffu, sum1, 2);
        float inv0 = 1.f / sum0, inv1 = 1.f / sum1;
        float* o0 = g_o + (size_t)(b*N + qb + g)*C + h*DH;
        float* o1 = o0 + 8*C;
        #pragma unroll
        for (int dt = 0; dt < 4; dt++) {
            *(float2*)&o0[dt*8 + 2*t] = make_float2(oacc[dt][0]*inv0, oacc[dt][1]*inv0);
            *(float2*)&o1[dt*8 + 2*t] = make_float2(oacc[dt][2]*inv1, oacc[dt][3]*inv1);
        }
    }
}

// ---------------------------------------------------------------------------
extern "C" void kernel_launch(void* const* d_in, const int* in_sizes, int n_in,
                              void* d_out, int out_size) {
    const float* pair   = (const float*)d_in[0];
    const int*   mask   = (const int*)  d_in[1];
    const float* ln_w   = (const float*)d_in[2];
    const float* ln_b   = (const float*)d_in[3];
    const float* w_bias = (const float*)d_in[4];
    const float* wq     = (const float*)d_in[5];
    const float* wk     = (const float*)d_in[6];
    const float* wv     = (const float*)d_in[7];
    const float* wg     = (const float*)d_in[8];
    const float* wo     = (const float*)d_in[9];

    cudaFuncSetAttribute(proj_mma_kernel, cudaFuncAttributeMaxDynamicSharedMemorySize,
                         PROJ_SMEM_BYTES);
    cudaFuncSetAttribute(out_mma_kernel, cudaFuncAttributeMaxDynamicSharedMemorySize,
                         PROJ_SMEM_BYTES);
    cudaFuncSetAttribute(attn_mma_kernel, cudaFuncAttributeMaxDynamicSharedMemorySize,
                         AT_SMEM);

    prep_w_kernel<<<5, 256>>>(wq, wk, wv, wg, wo);
    ln_bias_kernel<<<NN/16, 256>>>(pair, ln_w, ln_b, w_bias);
    proj_mma_kernel<<<NN/128, 256, PROJ_SMEM_BYTES>>>();
    attn_mma_kernel<<<dim3(N, H), 384, AT_SMEM>>>(mask);
    out_mma_kernel<<<NN/128, 256, PROJ_SMEM_BYTES>>>((float*)d_out);
}